// round 12
// baseline (speedup 1.0000x reference)
#include <cuda_runtime.h>
#include <cstddef>
#include <cstdint>

#define B   32
#define S   512
#define E   300
#define H   200
#define G3  600          // 3*H gate rows
#define GS  200          // gate slice per cluster CTA
#define LBL 10
#define ROWS (B*S)       // 16384

#define KT   16
#define PADW 132

typedef unsigned long long u64;

// ---------------- scratch (device globals: no allocations allowed) ----------
__device__ float g_gi [2u*ROWS*(size_t)G3];   // [dir][b*S+s][g]  ~78.6 MB
__device__ float g_wt [2*H*G3];               // w_hh transposed: [dir][k][g]
__device__ float g_hid[2u*ROWS*(size_t)H];    // hidden outputs   ~26.2 MB

// ---------------- f32x2 packed helpers ----------
__device__ __forceinline__ u64 pack2(float x, float y) {
    u64 r; asm("mov.b64 %0, {%1,%2};" : "=l"(r) : "f"(x), "f"(y)); return r;
}
__device__ __forceinline__ void unpack2(u64 v, float& x, float& y) {
    asm("mov.b64 {%0,%1}, %2;" : "=f"(x), "=f"(y) : "l"(v));
}
__device__ __forceinline__ void ffma2(u64& d, u64 a, u64 b) {
    asm("fma.rn.f32x2 %0, %1, %2, %0;" : "+l"(d) : "l"(a), "l"(b));
}
__device__ __forceinline__ void add2(u64& d, u64 a) {
    asm("add.rn.f32x2 %0, %0, %1;" : "+l"(d) : "l"(a));
}

// ---------------- cluster / DSMEM / mbarrier helpers ----------
__device__ __forceinline__ uint32_t s2u(const void* p) {
    uint32_t a;
    asm("{ .reg .u64 t; cvta.to.shared.u64 t, %1; cvt.u32.u64 %0, t; }"
        : "=r"(a) : "l"(p));
    return a;
}
__device__ __forceinline__ uint32_t mapa_u32(uint32_t a, uint32_t r) {
    uint32_t o;
    asm("mapa.shared::cluster.u32 %0, %1, %2;" : "=r"(o) : "r"(a), "r"(r));
    return o;
}
__device__ __forceinline__ uint32_t ctarank() {
    uint32_t r; asm("mov.u32 %0, %%cluster_ctarank;" : "=r"(r)); return r;
}
__device__ __forceinline__ void st_async64(uint32_t raddr, u64 v, uint32_t rmbar) {
    asm volatile(
        "st.async.shared::cluster.mbarrier::complete_tx::bytes.b64 [%0], %1, [%2];"
        :: "r"(raddr), "l"(v), "r"(rmbar) : "memory");
}
__device__ __forceinline__ void mbar_init(uint32_t a, uint32_t cnt) {
    asm volatile("mbarrier.init.shared.b64 [%0], %1;" :: "r"(a), "r"(cnt) : "memory");
}
__device__ __forceinline__ void mbar_arrive_expect_tx(uint32_t a, uint32_t bytes) {
    asm volatile("mbarrier.arrive.expect_tx.shared.b64 _, [%0], %1;"
                 :: "r"(a), "r"(bytes) : "memory");
}
__device__ __forceinline__ void mbar_wait(uint32_t a, uint32_t parity) {
    uint32_t done;
    asm volatile(
        "{\n\t.reg .pred p;\n\t"
        "mbarrier.try_wait.parity.acquire.cta.shared::cta.b64 p, [%1], %2;\n\t"
        "selp.b32 %0, 1, 0, p;\n\t}"
        : "=r"(done) : "r"(a), "r"(parity) : "memory");
    if (!done) {
        asm volatile(
            "{\n\t.reg .pred P1;\n\t"
            "WL_%=:\n\t"
            "mbarrier.try_wait.parity.acquire.cta.shared::cta.b64 P1, [%0], %1, 0x989680;\n\t"
            "@P1 bra.uni WD_%=;\n\t"
            "bra.uni WL_%=;\n\t"
            "WD_%=:\n\t}"
            :: "r"(a), "r"(parity) : "memory");
    }
}
#define CLUSTER_SYNC() do { \
    asm volatile("barrier.cluster.arrive.aligned;" ::: "memory"); \
    asm volatile("barrier.cluster.wait.aligned;" ::: "memory");   \
} while (0)

// ---------------- no-op shifter: keeps ncu's sampled slot on the rec --------
__global__ void shift_noop() {}

// ---------------- prep: transpose w_hh into [k][g] ----------
__global__ void prep_transpose(const float* __restrict__ wf,
                               const float* __restrict__ wb) {
    int i = blockIdx.x * blockDim.x + threadIdx.x;
    if (i < G3 * H) {
        int g = i / H, k = i - g * H;
        g_wt[k * G3 + g]          = wf[i];
        g_wt[H * G3 + k * G3 + g] = wb[i];
    }
}

// ---------------- gi = emb[text] @ w_ih^T + b_ih  (dup-B, zero-MOV loop) ---
// acc(m_even,m_odd) += (b,b) * (a_m0,a_m1).  B stored duplicated in a
// tx-contiguous layout: u64 index ((k*4+jp)*16 + tx)*2 + (g&1), g = tx*8+jp*2+(g&1).
__global__ void __launch_bounds__(256)
gi_gemm4(const int*   __restrict__ text,
         const float* __restrict__ emb,
         const float* __restrict__ wih_f,
         const float* __restrict__ bih_f,
         const float* __restrict__ wih_b,
         const float* __restrict__ bih_b) {
    const int d = blockIdx.z;
    const float* __restrict__ wih = d ? wih_b : wih_f;
    const float* __restrict__ bih = d ? bih_b : bih_f;

    __shared__ float As[KT][PADW];            // [k][m]
    __shared__ __align__(16) u64 Bs2[KT * 4 * 16 * 2];  // dup'd (b,b), 16 KB
    __shared__ int   tok[128];

    const int tid = threadIdx.x;
    const int by  = blockIdx.y;
    const int n0  = blockIdx.x * 128;

    if (tid < 128) tok[tid] = text[by * 128 + tid];
    __syncthreads();

    const int kq = tid & 3;
    const int m0 = tid >> 2;
    const int m1 = m0 + 64;
    const long ar0 = (long)tok[m0] * E;
    const long ar1 = (long)tok[m1] * E;
    const int  g0  = n0 + m0, g1 = n0 + m1;
    const bool vg0 = g0 < G3, vg1 = g1 < G3;

    // precomputed B-store sub-indices (per thread constants)
    const int bidx0 = (((m0 >> 1) & 3) * 16 + (m0 >> 3)) * 2 + (m0 & 1);
    const int bidx1 = (((m1 >> 1) & 3) * 16 + (m1 >> 3)) * 2 + (m1 & 1);

    const int ty = tid >> 4, tx = tid & 15;

    u64 acc[4][8];    // [m-pair][g]
    #pragma unroll
    for (int i = 0; i < 4; ++i)
        #pragma unroll
        for (int j = 0; j < 8; ++j) acc[i][j] = 0ULL;

    const float4 z4 = make_float4(0.f, 0.f, 0.f, 0.f);
    float4 aV0, aV1, bV0, bV1;

    {
        const int kk = kq * 4;
        aV0 = *(const float4*)&emb[ar0 + kk];
        aV1 = *(const float4*)&emb[ar1 + kk];
        bV0 = vg0 ? *(const float4*)&wih[(size_t)g0 * E + kk] : z4;
        bV1 = vg1 ? *(const float4*)&wih[(size_t)g1 * E + kk] : z4;
    }

    const int NT = (E + KT - 1) / KT;    // 19
    for (int t = 0; t < NT; ++t) {
        __syncthreads();
        As[kq*4+0][m0] = aV0.x; As[kq*4+1][m0] = aV0.y;
        As[kq*4+2][m0] = aV0.z; As[kq*4+3][m0] = aV0.w;
        As[kq*4+0][m1] = aV1.x; As[kq*4+1][m1] = aV1.y;
        As[kq*4+2][m1] = aV1.z; As[kq*4+3][m1] = aV1.w;
        // duplicated B stores: Bs2[(k*4)*32 + bidx]
        {
            const int kb = kq * 4;
            Bs2[(kb+0)*128 + bidx0] = pack2(bV0.x, bV0.x);
            Bs2[(kb+1)*128 + bidx0] = pack2(bV0.y, bV0.y);
            Bs2[(kb+2)*128 + bidx0] = pack2(bV0.z, bV0.z);
            Bs2[(kb+3)*128 + bidx0] = pack2(bV0.w, bV0.w);
            Bs2[(kb+0)*128 + bidx1] = pack2(bV1.x, bV1.x);
            Bs2[(kb+1)*128 + bidx1] = pack2(bV1.y, bV1.y);
            Bs2[(kb+2)*128 + bidx1] = pack2(bV1.z, bV1.z);
            Bs2[(kb+3)*128 + bidx1] = pack2(bV1.w, bV1.w);
        }
        __syncthreads();

        if (t + 1 < NT) {
            const int kk = (t + 1) * KT + kq * 4;
            const bool vk = kk < E;
            aV0 = vk ? *(const float4*)&emb[ar0 + kk] : z4;
            aV1 = vk ? *(const float4*)&emb[ar1 + kk] : z4;
            bV0 = (vk && vg0) ? *(const float4*)&wih[(size_t)g0 * E + kk] : z4;
            bV1 = (vk && vg1) ? *(const float4*)&wih[(size_t)g1 * E + kk] : z4;
        }

        #pragma unroll
        for (int k = 0; k < KT; ++k) {
            // A: 4 m-pairs, 2 LDS.128
            const ulonglong2* ap = (const ulonglong2*)&As[k][ty * 8];
            ulonglong2 av0 = ap[0], av1 = ap[1];
            u64 a2[4] = { av0.x, av0.y, av1.x, av1.y };
            // B: 8 dup'd g values, 4 LDS.128
            u64 bd[8];
            #pragma unroll
            for (int jp = 0; jp < 4; ++jp) {
                ulonglong2 bv = *(const ulonglong2*)&Bs2[k * 128 + jp * 32 + tx * 2];
                bd[2*jp]   = bv.x;
                bd[2*jp+1] = bv.y;
            }
            #pragma unroll
            for (int mp = 0; mp < 4; ++mp)
                #pragma unroll
                for (int gg = 0; gg < 8; ++gg)
                    ffma2(acc[mp][gg], bd[gg], a2[mp]);
        }
    }

    // epilogue: unpack m-pairs, add bias, store
    float* gout = g_gi + (size_t)d * ROWS * G3;
    #pragma unroll
    for (int mp = 0; mp < 4; ++mp) {
        const int row0 = by * 128 + ty * 8 + mp * 2;
        float o0[8], o1[8];
        #pragma unroll
        for (int gg = 0; gg < 8; ++gg) unpack2(acc[mp][gg], o0[gg], o1[gg]);
        #pragma unroll
        for (int gg = 0; gg < 8; ++gg) {
            const int g = n0 + tx * 8 + gg;
            if (g < G3) {
                gout[(size_t)row0 * G3 + g]       = o0[gg] + bih[g];
                gout[(size_t)(row0+1) * G3 + g]   = o1[gg] + bih[g];
            }
        }
    }
}

// ---------------- GRU recurrence: 3-CTA cluster, fully parallel phases ------
// (r11 version — measured 543 us. UNCHANGED.)
#define MAILW 608                 // floats per (buf,batch) mail slab
#define TXB   (G3 * 4)            // 2400 B per batch per step
__global__ void __launch_bounds__(512, 1) __cluster_dims__(3, 1, 1)
gru_rec7(const float* __restrict__ bhh_f, const float* __restrict__ bhh_b,
         const float* __restrict__ h0_f,  const float* __restrict__ h0_b) {
    __shared__ __align__(16) u64 hsd0[H];   // (h,h) per k, batch 0
    __shared__ __align__(16) u64 hsd1[H];   // batch 1
    __shared__ u64  redA[1000];             // [kc][g-pair] partials, batch 0
    __shared__ u64  redB[1000];             // batch 1
    __shared__ float mailf[4 * MAILW];      // [buf*2+batch][g]
    __shared__ u64  bo2[100];               // b_hh g-pairs
    __shared__ __align__(8) u64 mbar[4];    // [buf*2+batch]

    const int tid = threadIdx.x;
    const uint32_t rank = ctarank();
    const int group = blockIdx.x / 3;
    const int d  = group >> 4;
    const int b0 = (group & 15) * 2, b1 = b0 + 1;

    const float* bhh = d ? bhh_b : bhh_f;
    const float* h0  = d ? h0_b  : h0_f;

    // ---- weights into registers: 20 k x 4 g per thread, (g0,g1)(g2,g3) ----
    const float* wgd = g_wt + (size_t)d * (H * G3);
    const int kc = tid / 50;       // k-chunk of 20 (0..9)
    const int gq = tid % 50;       // g-quad
    const bool mv = tid < 500;
    u64 wreg[40];
    if (mv) {
        #pragma unroll
        for (int kk = 0; kk < 20; ++kk) {
            const float* wp = wgd + (size_t)(kc * 20 + kk) * G3 + rank * GS + gq * 4;
            wreg[2 * kk + 0] = *(const u64*)(wp);
            wreg[2 * kk + 1] = *(const u64*)(wp + 2);
        }
    }
    if (tid < 100)
        bo2[tid] = *(const u64*)(bhh + rank * GS + tid * 2);
    if (tid < H) {
        float a = (h0[b0 * H + tid] - 0.5f) * (1.0f / H);
        float c = (h0[b1 * H + tid] - 0.5f) * (1.0f / H);
        hsd0[tid] = pack2(a, a);
        hsd1[tid] = pack2(c, c);
    }
    const uint32_t mbar_u = s2u(mbar);
    if (tid == 0) {
        #pragma unroll
        for (int i = 0; i < 4; ++i) {
            mbar_init(mbar_u + i * 8, 1);
            mbar_arrive_expect_tx(mbar_u + i * 8, TXB);   // arm t=0 and t=1
        }
    }
    __syncthreads();
    CLUSTER_SYNC();        // peers' mbarriers armed before any st.async

    const size_t gbase0 = ((size_t)d * ROWS + (size_t)b0 * S) * G3;
    const size_t gbase1 = ((size_t)d * ROWS + (size_t)b1 * S) * G3;
    float* hid0 = g_hid + ((size_t)d * ROWS + (size_t)b0 * S) * H;
    float* hid1 = g_hid + ((size_t)d * ROWS + (size_t)b1 * S) * H;

    const uint32_t mail_u = s2u(mailf);
    const uint32_t mailR[3] = { mapa_u32(mail_u, 0), mapa_u32(mail_u, 1),
                                mapa_u32(mail_u, 2) };
    const uint32_t mbarR[3] = { mapa_u32(mbar_u, 0), mapa_u32(mbar_u, 1),
                                mapa_u32(mbar_u, 2) };

    // gate-group membership
    const bool gA = tid < 200;                    // gates b0, j = tid
    const bool gB = (tid >= 256) && (tid < 456);  // gates b1, j = tid-256
    const int  gj = gA ? tid : (tid - 256);

    for (int t = 0; t < S; ++t) {
        const int s   = d ? (S - 1 - t) : t;
        const int buf = t & 1;
        const uint32_t par = (t >> 1) & 1;

        // gi prefetch (each gate group loads its own batch)
        float gir_ = 0.f, giz_ = 0.f, gin_ = 0.f;
        if (gA | gB) {
            const float* p = g_gi + (gA ? gbase0 : gbase1) + (size_t)s * G3 + gj;
            gir_ = p[0]; giz_ = p[H]; gin_ = p[2 * H];
        }

        // ---- matvecs, both batches, no intervening barrier ----
        if (mv) {
            u64 a0 = 0, a1 = 0, c0 = 0, c1 = 0;
            const ulonglong2* hp0 = (const ulonglong2*)(hsd0 + kc * 20);
            const ulonglong2* hp1 = (const ulonglong2*)(hsd1 + kc * 20);
            #pragma unroll
            for (int kk = 0; kk < 10; ++kk) {
                ulonglong2 h2 = hp0[kk];
                ffma2(a0, wreg[4 * kk + 0], h2.x);
                ffma2(a1, wreg[4 * kk + 1], h2.x);
                ffma2(a0, wreg[4 * kk + 2], h2.y);
                ffma2(a1, wreg[4 * kk + 3], h2.y);
            }
            #pragma unroll
            for (int kk = 0; kk < 10; ++kk) {
                ulonglong2 h2 = hp1[kk];
                ffma2(c0, wreg[4 * kk + 0], h2.x);
                ffma2(c1, wreg[4 * kk + 1], h2.x);
                ffma2(c0, wreg[4 * kk + 2], h2.y);
                ffma2(c1, wreg[4 * kk + 3], h2.y);
            }
            redA[kc * 100 + gq * 2 + 0] = a0;
            redA[kc * 100 + gq * 2 + 1] = a1;
            redB[kc * 100 + gq * 2 + 0] = c0;
            redB[kc * 100 + gq * 2 + 1] = c1;
        }
        __syncthreads();                            // partials ready

        // ---- parallel reduce + push (b0: thr 0-99, b1: thr 128-227) ----
        if (tid < 100) {
            u64 sA = redA[tid];
            #pragma unroll
            for (int q = 1; q < 10; ++q) add2(sA, redA[q * 100 + tid]);
            add2(sA, bo2[tid]);
            const uint32_t off = (uint32_t)((buf * 2 + 0) * MAILW
                                            + rank * GS + tid * 2) * 4u;
            const uint32_t mboff = (uint32_t)(buf * 2 + 0) * 8u;
            #pragma unroll
            for (int rr = 0; rr < 3; ++rr)
                st_async64(mailR[rr] + off, sA, mbarR[rr] + mboff);
        } else if (tid >= 128 && tid < 228) {
            const int p = tid - 128;
            u64 sB = redB[p];
            #pragma unroll
            for (int q = 1; q < 10; ++q) add2(sB, redB[q * 100 + p]);
            add2(sB, bo2[p]);
            const uint32_t off = (uint32_t)((buf * 2 + 1) * MAILW
                                            + rank * GS + p * 2) * 4u;
            const uint32_t mboff = (uint32_t)(buf * 2 + 1) * 8u;
            #pragma unroll
            for (int rr = 0; rr < 3; ++rr)
                st_async64(mailR[rr] + off, sB, mbarR[rr] + mboff);
        }

        // ---- parallel wait + gates (fast-path math) ----
        if (gA | gB) {
            const int bslot = gA ? (buf * 2 + 0) : (buf * 2 + 1);
            mbar_wait(mbar_u + bslot * 8, par);
            if ((tid == 0 || tid == 256) && t + 2 < S)
                mbar_arrive_expect_tx(mbar_u + bslot * 8, TXB);
            const float* mb_ = mailf + bslot * MAILW;
            const float hr = mb_[gj], hz = mb_[H + gj], hn = mb_[2 * H + gj];
            u64* hsd = gA ? hsd0 : hsd1;
            float ho, dum; unpack2(hsd[gj], ho, dum);
            const float r = __fdividef(1.f, 1.f + __expf(-(gir_ + hr)));
            const float z = __fdividef(1.f, 1.f + __expf(-(giz_ + hz)));
            float xt = gin_ + r * hn;
            xt = fminf(fmaxf(xt, -30.f), 30.f);
            const float e = __expf(-2.f * xt);
            const float n = __fdividef(1.f - e, 1.f + e);
            const float hv = n + z * (ho - n);
            hsd[gj] = pack2(hv, hv);
            if (rank == 0)
                (gA ? hid0 : hid1)[(size_t)s * H + gj] = hv;
        }
        __syncthreads();                            // hsd stable for next mv
    }
}

// ---------------- final linear: warp per (b,s) row ----------
__global__ void preds_kernel(const float* __restrict__ lin_w,
                             const float* __restrict__ lin_b,
                             float* __restrict__ out) {
    __shared__ float lw[LBL * 2 * H];
    __shared__ float lb[LBL];
    const int tid = threadIdx.x;
    for (int i = tid; i < LBL * 2 * H; i += 256) lw[i] = lin_w[i];
    if (tid < LBL) lb[tid] = lin_b[tid];
    __syncthreads();

    const int wid = tid >> 5, lane = tid & 31;
    const int row = blockIdx.x * 8 + wid;
    const float* hf = g_hid + (size_t)row * H;
    const float* hb = g_hid + (size_t)(ROWS + row) * H;

    float acc[LBL] = {};
    for (int k = lane; k < 2 * H; k += 32) {
        float x = (k < H) ? hf[k] : hb[k - H];
        #pragma unroll
        for (int l = 0; l < LBL; ++l) acc[l] += x * lw[l * 2 * H + k];
    }
    #pragma unroll
    for (int l = 0; l < LBL; ++l) {
        float v = acc[l];
        #pragma unroll
        for (int o = 16; o > 0; o >>= 1) v += __shfl_xor_sync(0xffffffffu, v, o);
        if (lane == 0) out[(size_t)row * LBL + l] = v + lb[l];
    }
}

// ---------------- launch ----------
extern "C" void kernel_launch(void* const* d_in, const int* in_sizes, int n_in,
                              void* d_out, int out_size) {
    const int*   text  = (const int*)  d_in[0];
    const float* emb   = (const float*)d_in[1];
    const float* wih_f = (const float*)d_in[2];
    const float* whh_f = (const float*)d_in[3];
    const float* bih_f = (const float*)d_in[4];
    const float* bhh_f = (const float*)d_in[5];
    const float* wih_b = (const float*)d_in[6];
    const float* whh_b = (const float*)d_in[7];
    const float* bih_b = (const float*)d_in[8];
    const float* bhh_b = (const float*)d_in[9];
    const float* lin_w = (const float*)d_in[10];
    const float* lin_b = (const float*)d_in[11];
    const float* h0_f  = (const float*)d_in[12];
    const float* h0_b  = (const float*)d_in[13];
    float* out = (float*)d_out;

    shift_noop<<<1, 32>>>();   // keeps ncu's fixed sample slot on gru_rec7

    prep_transpose<<<(G3 * H + 255) / 256, 256>>>(whh_f, whh_b);

    dim3 gg((G3 + 127) / 128, ROWS / 128, 2);   // (5, 128, 2)
    gi_gemm4<<<gg, 256>>>(text, emb, wih_f, bih_f, wih_b, bih_b);

    gru_rec7<<<96, 512>>>(bhh_f, bhh_b, h0_f, h0_b);

    preds_kernel<<<ROWS / 8, 256>>>(lin_w, lin_b, out);
}

// round 13
// speedup vs baseline: 1.0799x; 1.0799x over previous
#include <cuda_runtime.h>
#include <cstddef>
#include <cstdint>

#define B   32
#define S   512
#define E   300
#define H   200
#define G3  600          // 3*H gate rows
#define GS  200          // gate slice per cluster CTA
#define LBL 10
#define ROWS (B*S)       // 16384

#define KT   16
#define PADW 132

typedef unsigned long long u64;

// ---------------- scratch (device globals: no allocations allowed) ----------
__device__ float g_gi [2u*ROWS*(size_t)G3];   // [dir][b*S+s][g]  ~78.6 MB
__device__ float g_wt [2*H*G3];               // w_hh transposed: [dir][k][g]
__device__ float g_hid[2u*ROWS*(size_t)H];    // hidden outputs   ~26.2 MB

// ---------------- f32x2 packed helpers ----------
__device__ __forceinline__ u64 pack2(float x, float y) {
    u64 r; asm("mov.b64 %0, {%1,%2};" : "=l"(r) : "f"(x), "f"(y)); return r;
}
__device__ __forceinline__ void unpack2(u64 v, float& x, float& y) {
    asm("mov.b64 {%0,%1}, %2;" : "=f"(x), "=f"(y) : "l"(v));
}
__device__ __forceinline__ void ffma2(u64& d, u64 a, u64 b) {
    asm("fma.rn.f32x2 %0, %1, %2, %0;" : "+l"(d) : "l"(a), "l"(b));
}
__device__ __forceinline__ void add2(u64& d, u64 a) {
    asm("add.rn.f32x2 %0, %0, %1;" : "+l"(d) : "l"(a));
}

// ---------------- cluster / DSMEM / mbarrier helpers ----------
__device__ __forceinline__ uint32_t s2u(const void* p) {
    uint32_t a;
    asm("{ .reg .u64 t; cvta.to.shared.u64 t, %1; cvt.u32.u64 %0, t; }"
        : "=r"(a) : "l"(p));
    return a;
}
__device__ __forceinline__ uint32_t mapa_u32(uint32_t a, uint32_t r) {
    uint32_t o;
    asm("mapa.shared::cluster.u32 %0, %1, %2;" : "=r"(o) : "r"(a), "r"(r));
    return o;
}
__device__ __forceinline__ uint32_t ctarank() {
    uint32_t r; asm("mov.u32 %0, %%cluster_ctarank;" : "=r"(r)); return r;
}
__device__ __forceinline__ void st_async64(uint32_t raddr, u64 v, uint32_t rmbar) {
    asm volatile(
        "st.async.shared::cluster.mbarrier::complete_tx::bytes.b64 [%0], %1, [%2];"
        :: "r"(raddr), "l"(v), "r"(rmbar) : "memory");
}
__device__ __forceinline__ void mbar_init(uint32_t a, uint32_t cnt) {
    asm volatile("mbarrier.init.shared.b64 [%0], %1;" :: "r"(a), "r"(cnt) : "memory");
}
__device__ __forceinline__ void mbar_arrive_expect_tx(uint32_t a, uint32_t bytes) {
    asm volatile("mbarrier.arrive.expect_tx.shared.b64 _, [%0], %1;"
                 :: "r"(a), "r"(bytes) : "memory");
}
__device__ __forceinline__ void mbar_wait(uint32_t a, uint32_t parity) {
    uint32_t done;
    asm volatile(
        "{\n\t.reg .pred p;\n\t"
        "mbarrier.try_wait.parity.acquire.cta.shared::cta.b64 p, [%1], %2;\n\t"
        "selp.b32 %0, 1, 0, p;\n\t}"
        : "=r"(done) : "r"(a), "r"(parity) : "memory");
    if (!done) {
        asm volatile(
            "{\n\t.reg .pred P1;\n\t"
            "WL_%=:\n\t"
            "mbarrier.try_wait.parity.acquire.cta.shared::cta.b64 P1, [%0], %1, 0x989680;\n\t"
            "@P1 bra.uni WD_%=;\n\t"
            "bra.uni WL_%=;\n\t"
            "WD_%=:\n\t}"
            :: "r"(a), "r"(parity) : "memory");
    }
}
#define CLUSTER_SYNC() do { \
    asm volatile("barrier.cluster.arrive.aligned;" ::: "memory"); \
    asm volatile("barrier.cluster.wait.aligned;" ::: "memory");   \
} while (0)

// ---------------- no-op shifter: keeps ncu's sampled slot on the rec --------
__global__ void shift_noop() {}

// ---------------- prep: transpose w_hh into [k][g] ----------
__global__ void prep_transpose(const float* __restrict__ wf,
                               const float* __restrict__ wb) {
    int i = blockIdx.x * blockDim.x + threadIdx.x;
    if (i < G3 * H) {
        int g = i / H, k = i - g * H;
        g_wt[k * G3 + g]          = wf[i];
        g_wt[H * G3 + k * G3 + g] = wb[i];
    }
}

// ---------------- gi = emb[text] @ w_ih^T + b_ih  (double-buffered tiles) --
// Inner loop identical to the measured-best gemm2 (FFMA2 pipe floor); the
// only change is 2-stage smem double buffering: ONE bar per k-tile.
__global__ void __launch_bounds__(256)
gi_gemm2(const int*   __restrict__ text,
         const float* __restrict__ emb,
         const float* __restrict__ wih_f,
         const float* __restrict__ bih_f,
         const float* __restrict__ wih_b,
         const float* __restrict__ bih_b) {
    const int d = blockIdx.z;
    const float* __restrict__ wih = d ? wih_b : wih_f;
    const float* __restrict__ bih = d ? bih_b : bih_f;

    __shared__ float As[2][KT][PADW];   // [buf][k][m]
    __shared__ float Bs[2][KT][PADW];   // [buf][k][n]
    __shared__ int   tok[128];

    const int tid = threadIdx.x;
    const int by  = blockIdx.y;
    const int n0  = blockIdx.x * 128;

    if (tid < 128) tok[tid] = text[by * 128 + tid];
    __syncthreads();

    const int kq = tid & 3;
    const int m0 = tid >> 2;
    const int m1 = m0 + 64;
    const long ar0 = (long)tok[m0] * E;
    const long ar1 = (long)tok[m1] * E;
    const int  g0  = n0 + m0, g1 = n0 + m1;
    const bool vg0 = g0 < G3, vg1 = g1 < G3;

    const int ty = tid >> 4, tx = tid & 15;

    u64 acc[8][4];
    #pragma unroll
    for (int i = 0; i < 8; ++i)
        #pragma unroll
        for (int j = 0; j < 4; ++j) acc[i][j] = 0ULL;

    const float4 z4 = make_float4(0.f, 0.f, 0.f, 0.f);
    float4 aV0, aV1, bV0, bV1;

    // prologue: load tile 0 regs and store into buf 0
    {
        const int kk = kq * 4;
        aV0 = *(const float4*)&emb[ar0 + kk];
        aV1 = *(const float4*)&emb[ar1 + kk];
        bV0 = vg0 ? *(const float4*)&wih[(size_t)g0 * E + kk] : z4;
        bV1 = vg1 ? *(const float4*)&wih[(size_t)g1 * E + kk] : z4;
        As[0][kq*4+0][m0] = aV0.x; As[0][kq*4+1][m0] = aV0.y;
        As[0][kq*4+2][m0] = aV0.z; As[0][kq*4+3][m0] = aV0.w;
        As[0][kq*4+0][m1] = aV1.x; As[0][kq*4+1][m1] = aV1.y;
        As[0][kq*4+2][m1] = aV1.z; As[0][kq*4+3][m1] = aV1.w;
        Bs[0][kq*4+0][m0] = bV0.x; Bs[0][kq*4+1][m0] = bV0.y;
        Bs[0][kq*4+2][m0] = bV0.z; Bs[0][kq*4+3][m0] = bV0.w;
        Bs[0][kq*4+0][m1] = bV1.x; Bs[0][kq*4+1][m1] = bV1.y;
        Bs[0][kq*4+2][m1] = bV1.z; Bs[0][kq*4+3][m1] = bV1.w;
    }
    __syncthreads();

    const int NT = (E + KT - 1) / KT;    // 19 (K padded to 304 with zeros)
    for (int t = 0; t < NT; ++t) {
        const int cb = t & 1;

        if (t + 1 < NT) {                // global prefetch of next tile
            const int kk = (t + 1) * KT + kq * 4;
            const bool vk = kk < E;
            aV0 = vk ? *(const float4*)&emb[ar0 + kk] : z4;
            aV1 = vk ? *(const float4*)&emb[ar1 + kk] : z4;
            bV0 = (vk && vg0) ? *(const float4*)&wih[(size_t)g0 * E + kk] : z4;
            bV1 = (vk && vg1) ? *(const float4*)&wih[(size_t)g1 * E + kk] : z4;
        }

        #pragma unroll
        for (int k = 0; k < KT; ++k) {
            float4 a0 = *(const float4*)&As[cb][k][ty * 8];
            float4 a1 = *(const float4*)&As[cb][k][ty * 8 + 4];
            float4 b0 = *(const float4*)&Bs[cb][k][tx * 8];
            float4 b1 = *(const float4*)&Bs[cb][k][tx * 8 + 4];
            u64 bp[4] = { pack2(b0.x, b0.y), pack2(b0.z, b0.w),
                          pack2(b1.x, b1.y), pack2(b1.z, b1.w) };
            float av[8] = { a0.x, a0.y, a0.z, a0.w, a1.x, a1.y, a1.z, a1.w };
            #pragma unroll
            for (int i = 0; i < 8; ++i) {
                u64 ap = pack2(av[i], av[i]);
                #pragma unroll
                for (int j = 0; j < 4; ++j) ffma2(acc[i][j], ap, bp[j]);
            }
        }

        if (t + 1 < NT) {                // store next tile into other buffer
            const int nb = cb ^ 1;
            As[nb][kq*4+0][m0] = aV0.x; As[nb][kq*4+1][m0] = aV0.y;
            As[nb][kq*4+2][m0] = aV0.z; As[nb][kq*4+3][m0] = aV0.w;
            As[nb][kq*4+0][m1] = aV1.x; As[nb][kq*4+1][m1] = aV1.y;
            As[nb][kq*4+2][m1] = aV1.z; As[nb][kq*4+3][m1] = aV1.w;
            Bs[nb][kq*4+0][m0] = bV0.x; Bs[nb][kq*4+1][m0] = bV0.y;
            Bs[nb][kq*4+2][m0] = bV0.z; Bs[nb][kq*4+3][m0] = bV0.w;
            Bs[nb][kq*4+0][m1] = bV1.x; Bs[nb][kq*4+1][m1] = bV1.y;
            Bs[nb][kq*4+2][m1] = bV1.z; Bs[nb][kq*4+3][m1] = bV1.w;
            __syncthreads();             // one bar per tile
        }
    }

    float* gout = g_gi + (size_t)d * ROWS * G3;
    #pragma unroll
    for (int i = 0; i < 8; ++i) {
        const int row = by * 128 + ty * 8 + i;
        float o[8];
        #pragma unroll
        for (int j = 0; j < 4; ++j) unpack2(acc[i][j], o[2*j], o[2*j+1]);
        #pragma unroll
        for (int j = 0; j < 8; ++j) {
            const int g = n0 + tx * 8 + j;
            if (g < G3)
                gout[(size_t)row * G3 + g] = o[j] + bih[g];
        }
    }
}

// ---------------- GRU recurrence: 3-CTA cluster, fully parallel phases ------
// (r11 version — measured 542 us. UNCHANGED.)
#define MAILW 608                 // floats per (buf,batch) mail slab
#define TXB   (G3 * 4)            // 2400 B per batch per step
__global__ void __launch_bounds__(512, 1) __cluster_dims__(3, 1, 1)
gru_rec7(const float* __restrict__ bhh_f, const float* __restrict__ bhh_b,
         const float* __restrict__ h0_f,  const float* __restrict__ h0_b) {
    __shared__ __align__(16) u64 hsd0[H];   // (h,h) per k, batch 0
    __shared__ __align__(16) u64 hsd1[H];   // batch 1
    __shared__ u64  redA[1000];             // [kc][g-pair] partials, batch 0
    __shared__ u64  redB[1000];             // batch 1
    __shared__ float mailf[4 * MAILW];      // [buf*2+batch][g]
    __shared__ u64  bo2[100];               // b_hh g-pairs
    __shared__ __align__(8) u64 mbar[4];    // [buf*2+batch]

    const int tid = threadIdx.x;
    const uint32_t rank = ctarank();
    const int group = blockIdx.x / 3;
    const int d  = group >> 4;
    const int b0 = (group & 15) * 2, b1 = b0 + 1;

    const float* bhh = d ? bhh_b : bhh_f;
    const float* h0  = d ? h0_b  : h0_f;

    // ---- weights into registers: 20 k x 4 g per thread, (g0,g1)(g2,g3) ----
    const float* wgd = g_wt + (size_t)d * (H * G3);
    const int kc = tid / 50;       // k-chunk of 20 (0..9)
    const int gq = tid % 50;       // g-quad
    const bool mv = tid < 500;
    u64 wreg[40];
    if (mv) {
        #pragma unroll
        for (int kk = 0; kk < 20; ++kk) {
            const float* wp = wgd + (size_t)(kc * 20 + kk) * G3 + rank * GS + gq * 4;
            wreg[2 * kk + 0] = *(const u64*)(wp);
            wreg[2 * kk + 1] = *(const u64*)(wp + 2);
        }
    }
    if (tid < 100)
        bo2[tid] = *(const u64*)(bhh + rank * GS + tid * 2);
    if (tid < H) {
        float a = (h0[b0 * H + tid] - 0.5f) * (1.0f / H);
        float c = (h0[b1 * H + tid] - 0.5f) * (1.0f / H);
        hsd0[tid] = pack2(a, a);
        hsd1[tid] = pack2(c, c);
    }
    const uint32_t mbar_u = s2u(mbar);
    if (tid == 0) {
        #pragma unroll
        for (int i = 0; i < 4; ++i) {
            mbar_init(mbar_u + i * 8, 1);
            mbar_arrive_expect_tx(mbar_u + i * 8, TXB);   // arm t=0 and t=1
        }
    }
    __syncthreads();
    CLUSTER_SYNC();        // peers' mbarriers armed before any st.async

    const size_t gbase0 = ((size_t)d * ROWS + (size_t)b0 * S) * G3;
    const size_t gbase1 = ((size_t)d * ROWS + (size_t)b1 * S) * G3;
    float* hid0 = g_hid + ((size_t)d * ROWS + (size_t)b0 * S) * H;
    float* hid1 = g_hid + ((size_t)d * ROWS + (size_t)b1 * S) * H;

    const uint32_t mail_u = s2u(mailf);
    const uint32_t mailR[3] = { mapa_u32(mail_u, 0), mapa_u32(mail_u, 1),
                                mapa_u32(mail_u, 2) };
    const uint32_t mbarR[3] = { mapa_u32(mbar_u, 0), mapa_u32(mbar_u, 1),
                                mapa_u32(mbar_u, 2) };

    // gate-group membership
    const bool gA = tid < 200;                    // gates b0, j = tid
    const bool gB = (tid >= 256) && (tid < 456);  // gates b1, j = tid-256
    const int  gj = gA ? tid : (tid - 256);

    for (int t = 0; t < S; ++t) {
        const int s   = d ? (S - 1 - t) : t;
        const int buf = t & 1;
        const uint32_t par = (t >> 1) & 1;

        // gi prefetch (each gate group loads its own batch)
        float gir_ = 0.f, giz_ = 0.f, gin_ = 0.f;
        if (gA | gB) {
            const float* p = g_gi + (gA ? gbase0 : gbase1) + (size_t)s * G3 + gj;
            gir_ = p[0]; giz_ = p[H]; gin_ = p[2 * H];
        }

        // ---- matvecs, both batches, no intervening barrier ----
        if (mv) {
            u64 a0 = 0, a1 = 0, c0 = 0, c1 = 0;
            const ulonglong2* hp0 = (const ulonglong2*)(hsd0 + kc * 20);
            const ulonglong2* hp1 = (const ulonglong2*)(hsd1 + kc * 20);
            #pragma unroll
            for (int kk = 0; kk < 10; ++kk) {
                ulonglong2 h2 = hp0[kk];
                ffma2(a0, wreg[4 * kk + 0], h2.x);
                ffma2(a1, wreg[4 * kk + 1], h2.x);
                ffma2(a0, wreg[4 * kk + 2], h2.y);
                ffma2(a1, wreg[4 * kk + 3], h2.y);
            }
            #pragma unroll
            for (int kk = 0; kk < 10; ++kk) {
                ulonglong2 h2 = hp1[kk];
                ffma2(c0, wreg[4 * kk + 0], h2.x);
                ffma2(c1, wreg[4 * kk + 1], h2.x);
                ffma2(c0, wreg[4 * kk + 2], h2.y);
                ffma2(c1, wreg[4 * kk + 3], h2.y);
            }
            redA[kc * 100 + gq * 2 + 0] = a0;
            redA[kc * 100 + gq * 2 + 1] = a1;
            redB[kc * 100 + gq * 2 + 0] = c0;
            redB[kc * 100 + gq * 2 + 1] = c1;
        }
        __syncthreads();                            // partials ready

        // ---- parallel reduce + push (b0: thr 0-99, b1: thr 128-227) ----
        if (tid < 100) {
            u64 sA = redA[tid];
            #pragma unroll
            for (int q = 1; q < 10; ++q) add2(sA, redA[q * 100 + tid]);
            add2(sA, bo2[tid]);
            const uint32_t off = (uint32_t)((buf * 2 + 0) * MAILW
                                            + rank * GS + tid * 2) * 4u;
            const uint32_t mboff = (uint32_t)(buf * 2 + 0) * 8u;
            #pragma unroll
            for (int rr = 0; rr < 3; ++rr)
                st_async64(mailR[rr] + off, sA, mbarR[rr] + mboff);
        } else if (tid >= 128 && tid < 228) {
            const int p = tid - 128;
            u64 sB = redB[p];
            #pragma unroll
            for (int q = 1; q < 10; ++q) add2(sB, redB[q * 100 + p]);
            add2(sB, bo2[p]);
            const uint32_t off = (uint32_t)((buf * 2 + 1) * MAILW
                                            + rank * GS + p * 2) * 4u;
            const uint32_t mboff = (uint32_t)(buf * 2 + 1) * 8u;
            #pragma unroll
            for (int rr = 0; rr < 3; ++rr)
                st_async64(mailR[rr] + off, sB, mbarR[rr] + mboff);
        }

        // ---- parallel wait + gates (fast-path math) ----
        if (gA | gB) {
            const int bslot = gA ? (buf * 2 + 0) : (buf * 2 + 1);
            mbar_wait(mbar_u + bslot * 8, par);
            if ((tid == 0 || tid == 256) && t + 2 < S)
                mbar_arrive_expect_tx(mbar_u + bslot * 8, TXB);
            const float* mb_ = mailf + bslot * MAILW;
            const float hr = mb_[gj], hz = mb_[H + gj], hn = mb_[2 * H + gj];
            u64* hsd = gA ? hsd0 : hsd1;
            float ho, dum; unpack2(hsd[gj], ho, dum);
            const float r = __fdividef(1.f, 1.f + __expf(-(gir_ + hr)));
            const float z = __fdividef(1.f, 1.f + __expf(-(giz_ + hz)));
            float xt = gin_ + r * hn;
            xt = fminf(fmaxf(xt, -30.f), 30.f);
            const float e = __expf(-2.f * xt);
            const float n = __fdividef(1.f - e, 1.f + e);
            const float hv = n + z * (ho - n);
            hsd[gj] = pack2(hv, hv);
            if (rank == 0)
                (gA ? hid0 : hid1)[(size_t)s * H + gj] = hv;
        }
        __syncthreads();                            // hsd stable for next mv
    }
}

// ---------------- final linear: warp per (b,s) row (float4 loads) ----------
__global__ void preds_kernel(const float* __restrict__ lin_w,
                             const float* __restrict__ lin_b,
                             float* __restrict__ out) {
    __shared__ __align__(16) float lw[LBL * 2 * H];
    __shared__ float lb[LBL];
    const int tid = threadIdx.x;
    for (int i = tid; i < LBL * 2 * H; i += 256) lw[i] = lin_w[i];
    if (tid < LBL) lb[tid] = lin_b[tid];
    __syncthreads();

    const int wid = tid >> 5, lane = tid & 31;
    const int row = blockIdx.x * 8 + wid;
    const float* hf = g_hid + (size_t)row * H;
    const float* hb = g_hid + (size_t)(ROWS + row) * H;

    float acc[LBL] = {};
    // 2H = 400 floats = 100 float4 chunks (first 50 from hf, next 50 from hb)
    for (int c = lane; c < 100; c += 32) {
        float4 x = (c < 50) ? *(const float4*)(hf + c * 4)
                            : *(const float4*)(hb + c * 4 - 200);
        #pragma unroll
        for (int l = 0; l < LBL; ++l) {
            float4 w = *(const float4*)&lw[l * 2 * H + c * 4];
            acc[l] += x.x * w.x + x.y * w.y + x.z * w.z + x.w * w.w;
        }
    }
    #pragma unroll
    for (int l = 0; l < LBL; ++l) {
        float v = acc[l];
        #pragma unroll
        for (int o = 16; o > 0; o >>= 1) v += __shfl_xor_sync(0xffffffffu, v, o);
        if (lane == 0) out[(size_t)row * LBL + l] = v + lb[l];
    }
}

// ---------------- launch ----------
extern "C" void kernel_launch(void* const* d_in, const int* in_sizes, int n_in,
                              void* d_out, int out_size) {
    const int*   text  = (const int*)  d_in[0];
    const float* emb   = (const float*)d_in[1];
    const float* wih_f = (const float*)d_in[2];
    const float* whh_f = (const float*)d_in[3];
    const float* bih_f = (const float*)d_in[4];
    const float* bhh_f = (const float*)d_in[5];
    const float* wih_b = (const float*)d_in[6];
    const float* whh_b = (const float*)d_in[7];
    const float* bih_b = (const float*)d_in[8];
    const float* bhh_b = (const float*)d_in[9];
    const float* lin_w = (const float*)d_in[10];
    const float* lin_b = (const float*)d_in[11];
    const float* h0_f  = (const float*)d_in[12];
    const float* h0_b  = (const float*)d_in[13];
    float* out = (float*)d_out;

    shift_noop<<<1, 32>>>();   // keeps ncu's fixed sample slot on gru_rec7

    prep_transpose<<<(G3 * H + 255) / 256, 256>>>(whh_f, whh_b);

    dim3 gg((G3 + 127) / 128, ROWS / 128, 2);   // (5, 128, 2)
    gi_gemm2<<<gg, 256>>>(text, emb, wih_f, bih_f, wih_b, bih_b);

    gru_rec7<<<96, 512>>>(bhh_f, bhh_b, h0_f, h0_b);

    preds_kernel<<<ROWS / 8, 256>>>(lin_w, lin_b, out);
}